// round 15
// baseline (speedup 1.0000x reference)
#include <cuda_runtime.h>
#include <cstddef>

// Arithmetic FROZEN (rel_err 2.10914e-4). R15: 3-deep smem K ring with split
// named barriers (producers run ahead; no lockstep), float4-paired scratch.

#define NN   4096
#define BM   8192
#define CH   32
#define NCH  (NN / CH)      // 128
#define RPC  64             // rows per CTA (2 chain warps)
#define TPB  128            // 2 chain + 2 producer warps
#define NBUF 3

__device__ float4 g_cu4[(size_t)(NN / 2) * BM];  // (c,u,c,u)[jpair][row]

// named barrier helpers
#define BAR_ARRIVE(id) asm volatile("bar.arrive %0, %1;" :: "r"(id), "r"(TPB) : "memory")
#define BAR_SYNC(id)   asm volatile("bar.sync   %0, %1;" :: "r"(id), "r"(TPB) : "memory")

__device__ __forceinline__ float rcp_refined(float d) {
    float r0;
    asm("rcp.approx.f32 %0, %1;" : "=f"(r0) : "f"(d));
    float e = __fmaf_rn(-d, r0, 1.0f);
    return __fmaf_rn(r0, e, r0);
}
__device__ __forceinline__ float div_rn_fast(float n, float d, float r) {
    float q0 = __fmul_rn(n, r);
    float rm = __fmaf_rn(-d, q0, n);
    return __fmaf_rn(rm, r, q0);
}

// ---- cephes exp, FMA-contracted (bit-frozen) ----
__device__ __forceinline__ float xla_expf_fma(float input) {
    const float exp_hi = 88.3762626647950f;
    const float exp_lo = -88.3762626647949f;
    const float LOG2EF = 1.44269504088896341f;
    const float C1 = 0.693359375f;
    const float C2 = -2.12194440e-4f;
    const float p0 = 1.9875691500E-4f;
    const float p1 = 1.3981999507E-3f;
    const float p2 = 8.3334519073E-3f;
    const float p3 = 4.1665795894E-2f;
    const float p4 = 1.6666665459E-1f;
    const float p5 = 5.0000001201E-1f;

    float x  = fmaxf(fminf(input, exp_hi), exp_lo);
    float fx = floorf(__fmaf_rn(x, LOG2EF, 0.5f));
    x = __fmaf_rn(-C1, fx, x);
    x = __fmaf_rn(-C2, fx, x);
    float z = __fmul_rn(x, x);

    float y = p0;
    y = __fmaf_rn(y, x, p1);
    y = __fmaf_rn(y, x, p2);
    y = __fmaf_rn(y, x, p3);
    y = __fmaf_rn(y, x, p4);
    y = __fmaf_rn(y, x, p5);
    y = __fmaf_rn(y, z, x);
    y = __fadd_rn(y, 1.0f);

    int n = (int)fx;
    float pow2n = __int_as_float((n + 127) << 23);
    return __fmul_rn(y, pow2n);
}

// ---- Thomas forward step (bit-frozen; shared reciprocal) ----
__device__ __forceinline__ void thomas_step(float K_cur, float K_next, float fj,
                                            float& c_prev, float& u_prev) {
    float s  = __fadd_rn(K_cur, K_next);
    float dn = __fmaf_rn(K_cur, c_prev, s);
    float r  = rcp_refined(dn);
    float c  = div_rn_fast(-K_next, dn, r);
    float u  = div_rn_fast(__fmaf_rn(K_cur, u_prev, fj), dn, r);
    c_prev = c; u_prev = u;
}

__global__ __launch_bounds__(TPB, 1) void thomas_kernel(
    const float* __restrict__ x, const float* __restrict__ f,
    float* __restrict__ out)
{
    __shared__ float sf[NN];
    __shared__ float sk[NBUF][RPC][CH + 1];

    const int tid  = threadIdx.x;
    const int wid  = tid >> 5;
    const int lane = tid & 31;
    const int rowBase = blockIdx.x * RPC;

    // stage f (all threads), one full barrier
    {
        const float4* f4 = reinterpret_cast<const float4*>(f);
        float4* sf4 = reinterpret_cast<float4*>(sf);
        for (int i = tid; i < NN / 4; i += TPB) sf4[i] = __ldg(&f4[i]);
    }
    __syncthreads();

    if (wid >= 2) {
        // ================= producer warps =================
        const int prow = (wid - 2) * 32 + lane;
        const float4* xr4 =
            reinterpret_cast<const float4*>(x + (size_t)(rowBase + prow) * NN);

        float4 tq[CH / 4];                        // x(chunk to convert next)
#pragma unroll
        for (int i = 0; i < CH / 4; ++i) tq[i] = __ldg(&xr4[i]);

        for (int ch = 0; ch < NCH; ++ch) {
            // prefetch x(ch+1)
            const int chp = (ch + 1 <= NCH - 1) ? (ch + 1) : (NCH - 1);
            float4 tqn[CH / 4];
#pragma unroll
            for (int i = 0; i < CH / 4; ++i)
                tqn[i] = __ldg(&xr4[chp * (CH / 4) + i]);

            const int s = ch % NBUF;
            if (ch >= NBUF) BAR_SYNC(4 + s);      // wait EMPTY_s
#pragma unroll
            for (int i = 0; i < CH / 4; ++i) {
                sk[s][prow][4 * i + 0] = xla_expf_fma(tq[i].x);
                sk[s][prow][4 * i + 1] = xla_expf_fma(tq[i].y);
                sk[s][prow][4 * i + 2] = xla_expf_fma(tq[i].z);
                sk[s][prow][4 * i + 3] = xla_expf_fma(tq[i].w);
            }
            asm volatile("membar.cta;" ::: "memory");
            BAR_ARRIVE(1 + s);                    // FULL_s
#pragma unroll
            for (int i = 0; i < CH / 4; ++i) tq[i] = tqn[i];
        }
        return;
    }

    // ================= chain warps =================
    const int crow = wid * 32 + lane;
    const int row  = rowBase + crow;

    float c_prev, u_prev, K_cur;
    float cs = 0.0f, us = 0.0f;                   // pending pair for STG.128

    {
        BAR_SYNC(1 + 0);                          // FULL_0
        float kk[CH], ff[CH];
#pragma unroll
        for (int i = 0; i < CH; ++i) kk[i] = sk[0][crow][i];
#pragma unroll
        for (int i = 0; i < CH; ++i) ff[i] = sf[i];

        float K0 = kk[0], K1 = kk[1];
        float d0 = __fmaf_rn(2.0f, K0, K1);
        float r0 = rcp_refined(d0);
        c_prev = div_rn_fast(-K1, d0, r0);
        u_prev = div_rn_fast(ff[0], d0, r0);
        cs = c_prev; us = u_prev;                 // j=0 pending
        K_cur = K1;

#pragma unroll
        for (int jj = 1; jj <= CH - 2; ++jj) {
            thomas_step(K_cur, kk[jj + 1], ff[jj], c_prev, u_prev);
            if (jj & 1)
                g_cu4[(size_t)(jj >> 1) * BM + row] =
                    make_float4(cs, us, c_prev, u_prev);
            else { cs = c_prev; us = u_prev; }
            K_cur = kk[jj + 1];
        }
        BAR_ARRIVE(4 + 0);                        // EMPTY_0
    }

    for (int ch = 1; ch < NCH; ++ch) {
        const int s  = ch % NBUF;
        const int jb = ch * CH - 1;               // first j of this chunk (odd)
        BAR_SYNC(1 + s);                          // FULL_s
        float kk[CH], ff[CH];
#pragma unroll
        for (int i = 0; i < CH; ++i) kk[i] = sk[s][crow][i];
#pragma unroll
        for (int i = 0; i < CH; ++i) ff[i] = sf[jb + i];

#pragma unroll
        for (int i = 0; i < CH; ++i) {
            const int j = jb + i;                 // parity: j odd when i even
            thomas_step(K_cur, kk[i], ff[i], c_prev, u_prev);
            if (j & 1)
                g_cu4[(size_t)(j >> 1) * BM + row] =
                    make_float4(cs, us, c_prev, u_prev);
            else { cs = c_prev; us = u_prev; }
            K_cur = kk[i];
        }
        BAR_ARRIVE(4 + s);                        // EMPTY_s
    }
    // j = NN-2 (even) is pending in (cs,us); final row j = NN-1:
    float den = __fmaf_rn(K_cur, c_prev, K_cur);
    float num = __fmaf_rn(K_cur, u_prev, sf[NN - 1]);
    float rl  = rcp_refined(den);
    float u_next = div_rn_fast(num, den, rl);
    // store last pair (c_{NN-2}, u_{NN-2}, c_{NN-1}=unused, u_{NN-1}=u_next)
    g_cu4[(size_t)((NN - 2) >> 1) * BM + row] =
        make_float4(cs, us, 0.0f, u_next);

    // ================= backward =================
    float4* __restrict__ o4 = reinterpret_cast<float4*>(out + (size_t)row * NN);

    float4 cua[CH / 2], cub[CH / 2];
#pragma unroll
    for (int i = 0; i < CH / 2; ++i)
        cua[i] = g_cu4[(size_t)((NCH - 1) * (CH / 2) + i) * BM + row];

    for (int ch = NCH - 1; ch >= 0; --ch) {
        const int chn = (ch > 0) ? (ch - 1) : 0;
#pragma unroll
        for (int i = 0; i < CH / 2; ++i)
            cub[i] = g_cu4[(size_t)(chn * (CH / 2) + i) * BM + row];

        float uq[4];
        if (ch == NCH - 1) {
            uq[3] = u_next;                       // j = 4095 = u_next itself
#pragma unroll
            for (int i = CH - 2; i >= 0; --i) {
                float cj = (i & 1) ? cua[i >> 1].z : cua[i >> 1].x;
                float uj = (i & 1) ? cua[i >> 1].w : cua[i >> 1].y;
                u_next = __fmaf_rn(-cj, u_next, uj);
                uq[i & 3] = u_next;
                if ((i & 3) == 0)
                    o4[ch * (CH / 4) + (i >> 2)] =
                        make_float4(uq[0], uq[1], uq[2], uq[3]);
            }
        } else {
#pragma unroll
            for (int i = CH - 1; i >= 0; --i) {
                float cj = (i & 1) ? cua[i >> 1].z : cua[i >> 1].x;
                float uj = (i & 1) ? cua[i >> 1].w : cua[i >> 1].y;
                u_next = __fmaf_rn(-cj, u_next, uj);
                uq[i & 3] = u_next;
                if ((i & 3) == 0)
                    o4[ch * (CH / 4) + (i >> 2)] =
                        make_float4(uq[0], uq[1], uq[2], uq[3]);
            }
        }
#pragma unroll
        for (int i = 0; i < CH / 2; ++i) cua[i] = cub[i];
    }
}

// ---------------------------------------------------------------------------
extern "C" void kernel_launch(void* const* d_in, const int* in_sizes, int n_in,
                              void* d_out, int out_size) {
    int ix = 0, if_ = 1;
    if (n_in >= 2 && in_sizes[1] > in_sizes[0]) { ix = 1; if_ = 0; }

    const float* x = (const float*)d_in[ix];
    const float* f = (const float*)d_in[if_];
    float* out     = (float*)d_out;

    const int n     = in_sizes[if_];        // 4096
    const int batch = in_sizes[ix] / n;     // 8192

    thomas_kernel<<<batch / RPC, TPB>>>(x, f, out);
}

// round 17
// speedup vs baseline: 1.0398x; 1.0398x over previous
#include <cuda_runtime.h>
#include <cstddef>

// Arithmetic FROZEN (rel_err 2.10914e-4). R16: split c-chain and u-chain
// across two warps. c-warp runs only the serial denominator/c recurrence
// (issue ~16 cyc/step << 40-cyc latency); u-warp (one chunk behind) redoes
// c bit-identically from the same (r,dn,K) inputs, computes u, and owns all
// scratch STG + the backward pass. Producers unchanged.

#define NN   4096
#define BM   8192
#define CH   32
#define NCH  (NN / CH)      // 128
#define RPC  32             // rows per CTA
#define TPB  128            // c-warp, u-warp, 2 producer warps
#define NBUF 3

__device__ float4 g_cu4[(size_t)(NN / 2) * BM];  // (c,u,c,u)[jpair][row]

#define BARC(id, cnt) asm volatile("bar.sync %0, %1;"   :: "r"(id), "r"(cnt) : "memory")
#define BARA(id, cnt) asm volatile("bar.arrive %0, %1;" :: "r"(id), "r"(cnt) : "memory")

__device__ __forceinline__ float rcp_refined(float d) {
    float r0;
    asm("rcp.approx.f32 %0, %1;" : "=f"(r0) : "f"(d));
    float e = __fmaf_rn(-d, r0, 1.0f);
    return __fmaf_rn(r0, e, r0);
}
__device__ __forceinline__ float div_rn_fast(float n, float d, float r) {
    float q0 = __fmul_rn(n, r);
    float rm = __fmaf_rn(-d, q0, n);
    return __fmaf_rn(rm, r, q0);
}

// ---- cephes exp, FMA-contracted (bit-frozen) ----
__device__ __forceinline__ float xla_expf_fma(float input) {
    const float exp_hi = 88.3762626647950f;
    const float exp_lo = -88.3762626647949f;
    const float LOG2EF = 1.44269504088896341f;
    const float C1 = 0.693359375f;
    const float C2 = -2.12194440e-4f;
    const float p0 = 1.9875691500E-4f;
    const float p1 = 1.3981999507E-3f;
    const float p2 = 8.3334519073E-3f;
    const float p3 = 4.1665795894E-2f;
    const float p4 = 1.6666665459E-1f;
    const float p5 = 5.0000001201E-1f;

    float x  = fmaxf(fminf(input, exp_hi), exp_lo);
    float fx = floorf(__fmaf_rn(x, LOG2EF, 0.5f));
    x = __fmaf_rn(-C1, fx, x);
    x = __fmaf_rn(-C2, fx, x);
    float z = __fmul_rn(x, x);

    float y = p0;
    y = __fmaf_rn(y, x, p1);
    y = __fmaf_rn(y, x, p2);
    y = __fmaf_rn(y, x, p3);
    y = __fmaf_rn(y, x, p4);
    y = __fmaf_rn(y, x, p5);
    y = __fmaf_rn(y, z, x);
    y = __fadd_rn(y, 1.0f);

    int n = (int)fx;
    float pow2n = __int_as_float((n + 127) << 23);
    return __fmul_rn(y, pow2n);
}

__global__ __launch_bounds__(TPB, 1) void thomas_kernel(
    const float* __restrict__ x, const float* __restrict__ f,
    float* __restrict__ out)
{
    __shared__ float  sf[NN];                    // 16 KB
    __shared__ float  sk[NBUF][RPC][CH + 1];     // 12.7 KB  K ring
    __shared__ float2 srd[2][CH + 1][RPC];       // 16.9 KB  (r, dn) ring

    const int tid  = threadIdx.x;
    const int wid  = tid >> 5;
    const int lane = tid & 31;
    const int rowBase = blockIdx.x * RPC;

    {   // stage f
        const float4* f4 = reinterpret_cast<const float4*>(f);
        float4* sf4 = reinterpret_cast<float4*>(sf);
        for (int i = tid; i < NN / 4; i += TPB) sf4[i] = __ldg(&f4[i]);
    }
    __syncthreads();

    if (wid >= 2) {
        // ================= producer warps (half columns each) =================
        const int half = wid - 2;
        const float4* xr4 =
            reinterpret_cast<const float4*>(x + (size_t)(rowBase + lane) * NN);

        float4 tq[4];
#pragma unroll
        for (int q = 0; q < 4; ++q) tq[q] = __ldg(&xr4[half * 4 + q]);

        for (int ch = 0; ch < NCH; ++ch) {
            const int chp = (ch + 1 <= NCH - 1) ? (ch + 1) : (NCH - 1);
            float4 tqn[4];
#pragma unroll
            for (int q = 0; q < 4; ++q)
                tqn[q] = __ldg(&xr4[chp * 8 + half * 4 + q]);

            const int s = ch % NBUF;
            if (ch >= NBUF) BARC(4 + s, 128);          // wait EMPTY_K
            const int c0 = half * 16;
#pragma unroll
            for (int q = 0; q < 4; ++q) {
                sk[s][lane][c0 + 4 * q + 0] = xla_expf_fma(tq[q].x);
                sk[s][lane][c0 + 4 * q + 1] = xla_expf_fma(tq[q].y);
                sk[s][lane][c0 + 4 * q + 2] = xla_expf_fma(tq[q].z);
                sk[s][lane][c0 + 4 * q + 3] = xla_expf_fma(tq[q].w);
            }
            asm volatile("membar.cta;" ::: "memory");
            BARA(1 + s, 96);                           // FULL_K
#pragma unroll
            for (int q = 0; q < 4; ++q) tq[q] = tqn[q];
        }
        return;
    }

    if (wid == 0) {
        // ================= c-warp: denominator / c chain only =================
        float c_prev = 0.0f, K_cur = 0.0f;
        for (int ch = 0; ch < NCH; ++ch) {
            const int s  = ch % NBUF;
            const int s2 = ch & 1;
            BARC(1 + s, 96);                           // FULL_K
            float kk[CH];
#pragma unroll
            for (int i = 0; i < CH; ++i) kk[i] = sk[s][lane][i];
            if (ch + NBUF < NCH) BARA(4 + s, 128);     // EMPTY_K (c part)

            if (ch == 0) {
                float d0 = __fmaf_rn(2.0f, kk[0], kk[1]);
                float r0 = rcp_refined(d0);
                c_prev   = div_rn_fast(-kk[1], d0, r0);
                srd[0][0][lane] = make_float2(r0, d0);
                K_cur = kk[1];
#pragma unroll
                for (int jj = 1; jj <= CH - 2; ++jj) {
                    float sS = __fadd_rn(K_cur, kk[jj + 1]);
                    float dn = __fmaf_rn(K_cur, c_prev, sS);
                    float r  = rcp_refined(dn);
                    c_prev   = div_rn_fast(-kk[jj + 1], dn, r);
                    srd[0][jj][lane] = make_float2(r, dn);
                    K_cur = kk[jj + 1];
                }
            } else {
#pragma unroll
                for (int i = 0; i < CH; ++i) {
                    float sS = __fadd_rn(K_cur, kk[i]);
                    float dn = __fmaf_rn(K_cur, c_prev, sS);
                    float r  = rcp_refined(dn);
                    c_prev   = div_rn_fast(-kk[i], dn, r);
                    srd[s2][i][lane] = make_float2(r, dn);
                    K_cur = kk[i];
                }
            }
            if (ch == NCH - 1) {                       // final-row denominator
                float den = __fmaf_rn(K_cur, c_prev, K_cur);
                float rl  = rcp_refined(den);
                srd[s2][CH][lane] = make_float2(rl, den);
            }
            BARC(7, 64);                               // c<->u handoff (drains STS)
        }
        return;
    }

    // ================= u-warp: u chain, scratch stores, backward =================
    const int row = rowBase + lane;
    float u_prev = 0.0f, K_cur = 0.0f;
    float cs = 0.0f, us = 0.0f;                        // pending even-j pair

    for (int ch = 0; ch < NCH; ++ch) {
        const int s  = ch % NBUF;
        const int s2 = ch & 1;
        BARC(7, 64);                                   // wait c-warp chunk ch

        float kk[CH];
#pragma unroll
        for (int i = 0; i < CH; ++i) kk[i] = sk[s][lane][i];
        if (ch + NBUF < NCH) BARA(4 + s, 128);         // EMPTY_K (u part)

        float2 rd[CH];
#pragma unroll
        for (int i = 0; i < CH; ++i) rd[i] = srd[s2][i][lane];

        if (ch == 0) {
            float ff[CH];
#pragma unroll
            for (int i = 0; i < CH; ++i) ff[i] = sf[i];

            float r0 = rd[0].x, d0 = rd[0].y;
            u_prev = div_rn_fast(ff[0], d0, r0);
            float c0 = div_rn_fast(-kk[1], d0, r0);    // bit-identical recompute
            cs = c0; us = u_prev;                      // j = 0 pending
            K_cur = kk[1];
#pragma unroll
            for (int jj = 1; jj <= CH - 2; ++jj) {
                float r = rd[jj].x, dn = rd[jj].y;
                float num = __fmaf_rn(K_cur, u_prev, ff[jj]);
                u_prev = div_rn_fast(num, dn, r);
                float c = div_rn_fast(-kk[jj + 1], dn, r);
                if (jj & 1)
                    g_cu4[(size_t)(jj >> 1) * BM + row] =
                        make_float4(cs, us, c, u_prev);
                else { cs = c; us = u_prev; }
                K_cur = kk[jj + 1];
            }
        } else {
            const int jb = ch * CH - 1;
            float ff[CH];
#pragma unroll
            for (int i = 0; i < CH; ++i) ff[i] = sf[jb + i];

#pragma unroll
            for (int i = 0; i < CH; ++i) {
                const int j = jb + i;
                float r = rd[i].x, dn = rd[i].y;
                float num = __fmaf_rn(K_cur, u_prev, ff[i]);
                u_prev = div_rn_fast(num, dn, r);
                float c = div_rn_fast(-kk[i], dn, r);
                if (j & 1)
                    g_cu4[(size_t)(j >> 1) * BM + row] =
                        make_float4(cs, us, c, u_prev);
                else { cs = c; us = u_prev; }
                K_cur = kk[i];
            }
        }
    }

    // final row j = NN-1 (K_cur == K[NN-1]; (rl,den) in extra slot of buf 1)
    float2 rl = srd[1][CH][lane];
    float num = __fmaf_rn(K_cur, u_prev, sf[NN - 1]);
    float u_next = div_rn_fast(num, rl.y, rl.x);
    g_cu4[(size_t)((NN - 2) >> 1) * BM + row] =
        make_float4(cs, us, 0.0f, u_next);

    // ================= backward =================
    float4* __restrict__ o4 = reinterpret_cast<float4*>(out + (size_t)row * NN);

    float4 cua[CH / 2], cub[CH / 2];
#pragma unroll
    for (int i = 0; i < CH / 2; ++i)
        cua[i] = g_cu4[(size_t)((NCH - 1) * (CH / 2) + i) * BM + row];

    for (int ch = NCH - 1; ch >= 0; --ch) {
        const int chn = (ch > 0) ? (ch - 1) : 0;
#pragma unroll
        for (int i = 0; i < CH / 2; ++i)
            cub[i] = g_cu4[(size_t)(chn * (CH / 2) + i) * BM + row];

        float uq[4];
        if (ch == NCH - 1) {
            uq[3] = u_next;                            // j = 4095
#pragma unroll
            for (int i = CH - 2; i >= 0; --i) {
                float cj = (i & 1) ? cua[i >> 1].z : cua[i >> 1].x;
                float uj = (i & 1) ? cua[i >> 1].w : cua[i >> 1].y;
                u_next = __fmaf_rn(-cj, u_next, uj);
                uq[i & 3] = u_next;
                if ((i & 3) == 0)
                    o4[ch * (CH / 4) + (i >> 2)] =
                        make_float4(uq[0], uq[1], uq[2], uq[3]);
            }
        } else {
#pragma unroll
            for (int i = CH - 1; i >= 0; --i) {
                float cj = (i & 1) ? cua[i >> 1].z : cua[i >> 1].x;
                float uj = (i & 1) ? cua[i >> 1].w : cua[i >> 1].y;
                u_next = __fmaf_rn(-cj, u_next, uj);
                uq[i & 3] = u_next;
                if ((i & 3) == 0)
                    o4[ch * (CH / 4) + (i >> 2)] =
                        make_float4(uq[0], uq[1], uq[2], uq[3]);
            }
        }
#pragma unroll
        for (int i = 0; i < CH / 2; ++i) cua[i] = cub[i];
    }
}

// ---------------------------------------------------------------------------
extern "C" void kernel_launch(void* const* d_in, const int* in_sizes, int n_in,
                              void* d_out, int out_size) {
    int ix = 0, if_ = 1;
    if (n_in >= 2 && in_sizes[1] > in_sizes[0]) { ix = 1; if_ = 0; }

    const float* x = (const float*)d_in[ix];
    const float* f = (const float*)d_in[if_];
    float* out     = (float*)d_out;

    const int n     = in_sizes[if_];        // 4096
    const int batch = in_sizes[ix] / n;     // 8192

    thomas_kernel<<<batch / RPC, TPB>>>(x, f, out);
}